// round 5
// baseline (speedup 1.0000x reference)
#include <cuda_runtime.h>

// Problem constants (UP=3, DOWN=2, Lh=63, Lb=51)
#define R_OUT 16                   // same-phase outputs per thread
#define BLOCK_T 384                // 3 phase groups x 128 threads
#define OUT_PER_BLOCK 6144         // 3 * 128 * R_OUT
#define TILE_X 4160                // logical floats per block (need 4154)
#define XS_PHYS 5200               // XP(TILE_X)
#define OS_PHYS 6272               // 6144 + 6144/48
#define SBUF_SZ 6272               // max(XS_PHYS, OS_PHYS)
#define NSTEP 29                   // packed coefficient steps per phase

// xs swizzle: pad FOUR floats per 16 -> lane stride 32 becomes phys stride 40
// (10*l mod 32 all-distinct -> LDS.64 conflict-free) and logical 4-aligned
// indices stay 16B-aligned (pad is a multiple of 4).
#define XP(i) ((i) + (((i) >> 4) << 2))

__device__ __forceinline__ unsigned long long fma_f32x2(
    unsigned long long a, unsigned long long bb, unsigned long long c) {
    unsigned long long d;
    asm("fma.rn.f32x2 %0, %1, %2, %3;" : "=l"(d) : "l"(a), "l"(bb), "l"(c));
    return d;
}

// Exact two-stage value for edge outputs (head j<50 where u-padding matters,
// tail j>=n_out where appended zeros matter).
__device__ float edge_value(const float* __restrict__ x,
                            const float* __restrict__ h,
                            const float* __restrict__ b,
                            long long j, int n_in, long long n_out) {
    float acc = 0.0f;
    for (int s = 0; s < 51; s++) {
        long long k = j - s;
        if (k < 0 || k >= n_out) continue;
        long long mlo = (2 * k - 30 + 2) / 3;
        if (mlo < 0) mlo = 0;
        long long mhi = (2 * k + 32) / 3;
        if (mhi > (long long)n_in - 1) mhi = (long long)n_in - 1;
        float u = 0.0f;
        for (long long m = mlo; m <= mhi; m++) {
            long long hi = 2 * k + 32 - 3 * m;
            if (hi >= 0 && hi < 63) u = fmaf(x[m], h[hi], u);
        }
        acc = fmaf(b[s], u, acc);
    }
    return acc;
}

// Fused single kernel.
// out[j] = sum_m x[m]*C[2j+32-3m], C[r] = sum_s b[s]*h[r-2s] (r in [0,163)).
// Group g = tid/128 handles j == g (mod 3); each thread: 16 outputs
// j = jbase + g + 3*(16*l + d) via f32x2 packed FMAs over a circular
// 16-pair register window on a bank-swizzled smem tile.
__global__ void __launch_bounds__(BLOCK_T) fused_kernel(
    const float* __restrict__ x, const float* __restrict__ h,
    const float* __restrict__ b, float* __restrict__ out,
    int n_in, int n_out, int out_total)
{
    __shared__ float sbuf[SBUF_SZ];   // xs (phase 1) then os (phase 2)
    __shared__ float C[164];
    __shared__ unsigned long long cs[3][NSTEP];

    float* xs = sbuf;
    float* os = sbuf;

    int tid = threadIdx.x;
    int bx = blockIdx.x;
    int jbase = bx * OUT_PER_BLOCK;
    int g0 = (jbase / 3) * 2 - 45;  // global x index of logical xs[0]

    // --- per-block coefficient computation ---
    if (tid < 163) {
        float acc = 0.0f;
        #pragma unroll
        for (int s = 0; s < 51; s++) {
            int idx = tid - 2 * s;
            if (idx >= 0 && idx < 63) acc = fmaf(b[s], h[idx], acc);
        }
        C[tid] = acc;
    }

    // --- input tile load (interior blocks: no bounds checks) ---
    if (bx != 0 && bx != (int)gridDim.x - 1) {
        #pragma unroll
        for (int q = tid; q < TILE_X; q += BLOCK_T)
            xs[XP(q)] = __ldg(&x[g0 + q]);
    } else {
        #pragma unroll
        for (int q = tid; q < TILE_X; q += BLOCK_T) {
            int idx = g0 + q;
            xs[XP(q)] = (idx >= 0 && idx < n_in) ? x[idx] : 0.0f;
        }
    }
    __syncthreads();

    // --- pack per-phase coefficient pairs ---
    // cs[g][t] = (K'[2t], K'[2t+1]), K'[v] = K[v - (g&1)], K[u] = C[(2-g) + 3*(55-u)]
    if (tid < 3 * NSTEP) {
        int g = tid / NSTEP, t = tid % NSTEP;
        int p = 2 - g, e = g & 1;
        float hv[2];
        #pragma unroll
        for (int q = 0; q < 2; q++) {
            int u = 2 * t + q - e;
            float val = 0.0f;
            if (u >= 0 && u <= 55) {
                int idx = p + 3 * (55 - u);
                if (idx <= 162) val = C[idx];
            }
            hv[q] = val;
        }
        cs[g][t] = (unsigned long long)__float_as_uint(hv[0]) |
                   ((unsigned long long)__float_as_uint(hv[1]) << 32);
    }
    __syncthreads();

    // --- main packed FIR loop ---
    int g = tid >> 7;
    int l = tid & 127;
    int E0 = (g & 2) + (l << 5);  // even window base (g=1 shift folded into coeffs)

    unsigned long long w2[16];
    #pragma unroll
    for (int k = 0; k < 16; k++)
        w2[k] = *(const unsigned long long*)&xs[XP(E0 + 2 * k)];

    unsigned long long acc2[R_OUT];
    #pragma unroll
    for (int d = 0; d < R_OUT; d++) acc2[d] = 0ull;

    const unsigned long long* cp = cs[g];

    #pragma unroll
    for (int t = 0; t < NSTEP; t++) {
        unsigned long long c = cp[t];
        #pragma unroll
        for (int d = 0; d < R_OUT; d++)
            acc2[d] = fma_f32x2(w2[(t + d) & 15], c, acc2[d]);
        if (t < NSTEP - 1)
            w2[t & 15] = *(const unsigned long long*)&xs[XP(E0 + 2 * (t + 16))];
    }

    __syncthreads();  // all xs reads done; sbuf becomes os

    // --- stage outputs: logical o = g + 48*l + 3*d, phys = o + o/48 = 49*l + g + 3*d ---
    #pragma unroll
    for (int d = 0; d < R_OUT; d++) {
        float lo = __uint_as_float((unsigned)(acc2[d] & 0xffffffffull));
        float hi = __uint_as_float((unsigned)(acc2[d] >> 32));
        os[49 * l + g + 3 * d] = lo + hi;
    }
    __syncthreads();

    // --- coalesced vectorized writeback ---
    if (jbase >= 50 && jbase + OUT_PER_BLOCK <= n_out) {
        #pragma unroll
        for (int it = 0; it < OUT_PER_BLOCK / (4 * BLOCK_T); it++) {
            int q4 = 4 * (tid + it * BLOCK_T);
            float4 v;
            v.x = os[q4 + q4 / 48];
            v.y = os[(q4 + 1) + (q4 + 1) / 48];
            v.z = os[(q4 + 2) + (q4 + 2) / 48];
            v.w = os[(q4 + 3) + (q4 + 3) / 48];
            *(float4*)&out[jbase + q4] = v;
        }
    } else {
        #pragma unroll
        for (int q = tid; q < OUT_PER_BLOCK; q += BLOCK_T) {
            int j = jbase + q;
            // j >= 50 (head handled exactly below) and j < n_out
            if ((unsigned)(j - 50) < (unsigned)(n_out - 50)) out[j] = os[q + q / 48];
        }
    }

    // --- block 0: exact edge outputs (head + tail) ---
    if (bx == 0) {
        int n_tail = out_total - n_out;
        if (tid < 50 + n_tail) {
            long long j = (tid < 50) ? (long long)tid
                                     : (long long)n_out + (tid - 50);
            out[j] = edge_value(x, h, b, j, n_in, (long long)n_out);
        }
    }
}

extern "C" void kernel_launch(void* const* d_in, const int* in_sizes, int n_in_arrs,
                              void* d_out, int out_size) {
    const float* x = (const float*)d_in[0];
    const float* h = (const float*)d_in[1];
    const float* b = (const float*)d_in[2];
    float* out = (float*)d_out;

    int n_in = in_sizes[0];  // 8 * 1048576 = 8388608
    long long n3 = (long long)n_in * 3;
    long long n_out = n3 / 2 + ((n3 % 2) ? 1 : 0);  // 12582912
    int out_total = out_size;                        // 12583008

    int grid = (int)((n_out + OUT_PER_BLOCK - 1) / OUT_PER_BLOCK);  // 2048
    fused_kernel<<<grid, BLOCK_T>>>(x, h, b, out, n_in, (int)n_out, out_total);
}

// round 6
// speedup vs baseline: 1.1601x; 1.1601x over previous
#include <cuda_runtime.h>

// Problem constants (UP=3, DOWN=2, Lh=63, Lb=51)
#define R_OUT 16                   // same-phase outputs per thread
#define BLOCK_T 384                // 3 phase groups x 128 threads
#define OUT_PER_BLOCK 6144         // 3 * 128 * R_OUT
#define TILE_X 4160                // logical floats per block (need 4154)
#define XS_PHYS 4420               // XP(TILE_X) upper bound
#define OS_PHYS 6272               // 6144 + 6144/48
#define SBUF_SZ 6272               // max(XS_PHYS, OS_PHYS)
#define NSTEP 29                   // packed coefficient steps per phase

// xs swizzle: pad TWO floats per 32 -> lane logical stride 32 becomes phys
// stride 34 (= 2 mod 32 banks: each 16-lane LDS.64 phase hits 16 distinct
// bank-pairs -> conflict-free), pad is even so 8B alignment is preserved.
#define XP(i) ((i) + (((i) >> 5) << 1))

__device__ __forceinline__ unsigned long long fma_f32x2(
    unsigned long long a, unsigned long long bb, unsigned long long c) {
    unsigned long long d;
    asm("fma.rn.f32x2 %0, %1, %2, %3;" : "=l"(d) : "l"(a), "l"(bb), "l"(c));
    return d;
}

// Exact two-stage value for edge outputs (head j<50 where u-padding matters,
// tail j>=n_out where appended zeros matter).
__device__ float edge_value(const float* __restrict__ x,
                            const float* __restrict__ h,
                            const float* __restrict__ b,
                            long long j, int n_in, long long n_out) {
    float acc = 0.0f;
    for (int s = 0; s < 51; s++) {
        long long k = j - s;
        if (k < 0 || k >= n_out) continue;
        long long mlo = (2 * k - 30 + 2) / 3;
        if (mlo < 0) mlo = 0;
        long long mhi = (2 * k + 32) / 3;
        if (mhi > (long long)n_in - 1) mhi = (long long)n_in - 1;
        float u = 0.0f;
        for (long long m = mlo; m <= mhi; m++) {
            long long hi = 2 * k + 32 - 3 * m;
            if (hi >= 0 && hi < 63) u = fmaf(x[m], h[hi], u);
        }
        acc = fmaf(b[s], u, acc);
    }
    return acc;
}

// Fused single kernel.
// out[j] = sum_m x[m]*C[2j+32-3m], C[r] = sum_s b[s]*h[r-2s] (r in [0,163)).
// Group g = tid/128 handles j == g (mod 3); each thread: 16 outputs
// j = jbase + g + 3*(16*l + d) via f32x2 packed FMAs over a circular
// 16-pair register window on a bank-swizzled smem tile.
__global__ void __launch_bounds__(BLOCK_T) fused_kernel(
    const float* __restrict__ x, const float* __restrict__ h,
    const float* __restrict__ b, float* __restrict__ out,
    int n_in, int n_out, int out_total)
{
    __shared__ float sbuf[SBUF_SZ];   // xs (phase 1) then os (phase 2)
    __shared__ float C[164];
    __shared__ unsigned long long cs[3][NSTEP];

    float* xs = sbuf;
    float* os = sbuf;

    int tid = threadIdx.x;
    int bx = blockIdx.x;
    int jbase = bx * OUT_PER_BLOCK;
    int g0 = (jbase / 3) * 2 - 45;  // global x index of logical xs[0]

    // --- per-block coefficient computation ---
    if (tid < 163) {
        float acc = 0.0f;
        #pragma unroll
        for (int s = 0; s < 51; s++) {
            int idx = tid - 2 * s;
            if (idx >= 0 && idx < 63) acc = fmaf(b[s], h[idx], acc);
        }
        C[tid] = acc;
    }

    // --- input tile load (interior blocks: no bounds checks) ---
    if (bx != 0 && bx != (int)gridDim.x - 1) {
        #pragma unroll
        for (int q = tid; q < TILE_X; q += BLOCK_T)
            xs[XP(q)] = __ldg(&x[g0 + q]);
    } else {
        #pragma unroll
        for (int q = tid; q < TILE_X; q += BLOCK_T) {
            int idx = g0 + q;
            xs[XP(q)] = (idx >= 0 && idx < n_in) ? x[idx] : 0.0f;
        }
    }
    __syncthreads();

    // --- pack per-phase coefficient pairs ---
    // cs[g][t] = (K'[2t], K'[2t+1]), K'[v] = K[v - (g&1)], K[u] = C[(2-g) + 3*(55-u)]
    if (tid < 3 * NSTEP) {
        int g = tid / NSTEP, t = tid % NSTEP;
        int p = 2 - g, e = g & 1;
        float hv[2];
        #pragma unroll
        for (int q = 0; q < 2; q++) {
            int u = 2 * t + q - e;
            float val = 0.0f;
            if (u >= 0 && u <= 55) {
                int idx = p + 3 * (55 - u);
                if (idx <= 162) val = C[idx];
            }
            hv[q] = val;
        }
        cs[g][t] = (unsigned long long)__float_as_uint(hv[0]) |
                   ((unsigned long long)__float_as_uint(hv[1]) << 32);
    }
    __syncthreads();

    // --- main packed FIR loop ---
    int g = tid >> 7;
    int l = tid & 127;
    int E0 = (g & 2) + (l << 5);  // even window base (g=1 shift folded into coeffs)

    unsigned long long w2[16];
    #pragma unroll
    for (int k = 0; k < 16; k++)
        w2[k] = *(const unsigned long long*)&xs[XP(E0 + 2 * k)];

    unsigned long long acc2[R_OUT];
    #pragma unroll
    for (int d = 0; d < R_OUT; d++) acc2[d] = 0ull;

    const unsigned long long* cp = cs[g];

    #pragma unroll
    for (int t = 0; t < NSTEP; t++) {
        unsigned long long c = cp[t];
        #pragma unroll
        for (int d = 0; d < R_OUT; d++)
            acc2[d] = fma_f32x2(w2[(t + d) & 15], c, acc2[d]);
        if (t < NSTEP - 1)
            w2[t & 15] = *(const unsigned long long*)&xs[XP(E0 + 2 * (t + 16))];
    }

    __syncthreads();  // all xs reads done; sbuf becomes os

    // --- stage outputs: logical o = g + 48*l + 3*d, phys = o + o/48 = 49*l + g + 3*d ---
    #pragma unroll
    for (int d = 0; d < R_OUT; d++) {
        float lo = __uint_as_float((unsigned)(acc2[d] & 0xffffffffull));
        float hi = __uint_as_float((unsigned)(acc2[d] >> 32));
        os[49 * l + g + 3 * d] = lo + hi;
    }
    __syncthreads();

    // --- coalesced vectorized writeback ---
    if (jbase >= 50 && jbase + OUT_PER_BLOCK <= n_out) {
        #pragma unroll
        for (int it = 0; it < OUT_PER_BLOCK / (4 * BLOCK_T); it++) {
            int q4 = 4 * (tid + it * BLOCK_T);
            float4 v;
            v.x = os[q4 + q4 / 48];
            v.y = os[(q4 + 1) + (q4 + 1) / 48];
            v.z = os[(q4 + 2) + (q4 + 2) / 48];
            v.w = os[(q4 + 3) + (q4 + 3) / 48];
            *(float4*)&out[jbase + q4] = v;
        }
    } else {
        #pragma unroll
        for (int q = tid; q < OUT_PER_BLOCK; q += BLOCK_T) {
            int j = jbase + q;
            // j >= 50 (head handled exactly below) and j < n_out
            if ((unsigned)(j - 50) < (unsigned)(n_out - 50)) out[j] = os[q + q / 48];
        }
    }

    // --- block 0: exact edge outputs (head + tail) ---
    if (bx == 0) {
        int n_tail = out_total - n_out;
        if (tid < 50 + n_tail) {
            long long j = (tid < 50) ? (long long)tid
                                     : (long long)n_out + (tid - 50);
            out[j] = edge_value(x, h, b, j, n_in, (long long)n_out);
        }
    }
}

extern "C" void kernel_launch(void* const* d_in, const int* in_sizes, int n_in_arrs,
                              void* d_out, int out_size) {
    const float* x = (const float*)d_in[0];
    const float* h = (const float*)d_in[1];
    const float* b = (const float*)d_in[2];
    float* out = (float*)d_out;

    int n_in = in_sizes[0];  // 8 * 1048576 = 8388608
    long long n3 = (long long)n_in * 3;
    long long n_out = n3 / 2 + ((n3 % 2) ? 1 : 0);  // 12582912
    int out_total = out_size;                        // 12583008

    int grid = (int)((n_out + OUT_PER_BLOCK - 1) / OUT_PER_BLOCK);  // 2048
    fused_kernel<<<grid, BLOCK_T>>>(x, h, b, out, n_in, (int)n_out, out_total);
}